// round 9
// baseline (speedup 1.0000x reference)
#include <cuda_runtime.h>
#include <cuda_bf16.h>
#include <math.h>
#include <stdint.h>

// Problem constants
#define Bc   8
#define Sc   1024
#define Dc   512
#define Hc   2048
#define Ec   8
#define Tc   8192   // B*S tokens

// moe tiling: CTA = 128 entries x 256-col chunks, K staged 64 at a time
#define MT     128
#define NCHK   256                 // cols per chunk
#define KB     64                  // K elems per stage (128B rows)
#define NCHUNK (Hc / NCHK)         // 8
#define NKB    (Dc / KB)           // 8
#define NITER  (NCHUNK * NKB)      // 64

// SMEM stage layout (bytes), 3-stage pipeline
#define OFF_A   0
#define OFF_B   (16 * 1024)
#define BUF_BYTES (48 * 1024)
#define DYN_SMEM (3 * BUF_BYTES)

// ---------------- device scratch ----------------
__device__ int    g_cnt[Ec];
__device__ int    g_tok[Ec * Tc];
__device__ float  g_wgt[Ec * Tc];
__device__ float  g_zpart[Tc * 2];
__device__ float  g_w2sum[Ec * Hc];
__device__ float  g_b2sum[Ec];
__device__ __nv_bfloat16 g_w1h[(size_t)Ec * Hc * Dc];   // [e][h][d] K-major, bf16
__device__ __nv_bfloat16 g_xh[(size_t)Tc * Dc];         // bf16(x)

// ---------------- helpers ----------------
__device__ __forceinline__ uint32_t smem_u32(const void* p) {
    uint32_t a;
    asm("{ .reg .u64 t; cvta.to.shared.u64 t, %1; cvt.u32.u64 %0, t; }" : "=r"(a) : "l"(p));
    return a;
}
#define SWZ(off) ((off) ^ (((off) >> 3) & 0x70))

#define CP_ASYNC16(dst, src) \
    asm volatile("cp.async.cg.shared.global [%0], [%1], 16;" :: "r"(dst), "l"(src))
#define CP_COMMIT() asm volatile("cp.async.commit_group;" ::: "memory")
#define CP_WAIT1()  asm volatile("cp.async.wait_group 1;" ::: "memory")

__device__ __forceinline__ void ldsm_x4(uint32_t addr, uint32_t& r0, uint32_t& r1,
                                        uint32_t& r2, uint32_t& r3) {
    asm volatile("ldmatrix.sync.aligned.m8n8.x4.shared.b16 {%0,%1,%2,%3}, [%4];"
                 : "=r"(r0), "=r"(r1), "=r"(r2), "=r"(r3) : "r"(addr));
}
__device__ __forceinline__ void mma16816(float* c, const uint32_t* a, const uint32_t* b) {
    asm volatile("mma.sync.aligned.m16n8k16.row.col.f32.bf16.bf16.f32 "
                 "{%0,%1,%2,%3}, {%4,%5,%6,%7}, {%8,%9}, {%0,%1,%2,%3};"
                 : "+f"(c[0]), "+f"(c[1]), "+f"(c[2]), "+f"(c[3])
                 : "r"(a[0]), "r"(a[1]), "r"(a[2]), "r"(a[3]), "r"(b[0]), "r"(b[1]));
}

// ================= fused prep kernel =================
// blockIdx ranges:
//   [0, 2048)        : x -> bf16
//   [2048, 10240)    : w1 transpose + bf16 convert
//   [10240, 12288)   : w2sum
//   [12288, 13312)   : gate
//   [13312]          : b2sum
#define PREP_BLOCKS 13313

__global__ void prep_kernel(const float* __restrict__ x,
                            const float* __restrict__ gw,
                            const float* __restrict__ gb,
                            const float* __restrict__ w1,
                            const float* __restrict__ w2,
                            const float* __restrict__ b2) {
    __shared__ float sh[4096];   // 16 KB, aliased per section
    const int bid = blockIdx.x;
    const int tid = threadIdx.x;

    if (bid < 2048) {
        // ---- x -> bf16 (8 floats per thread) ----
        size_t i = ((size_t)bid * 256 + tid) * 8;
        float4 v0 = *(const float4*)(x + i);
        float4 v1 = *(const float4*)(x + i + 4);
        __nv_bfloat162 hA = __floats2bfloat162_rn(v0.x, v0.y);
        __nv_bfloat162 hB = __floats2bfloat162_rn(v0.z, v0.w);
        __nv_bfloat162 hC = __floats2bfloat162_rn(v1.x, v1.y);
        __nv_bfloat162 hD = __floats2bfloat162_rn(v1.z, v1.w);
        uint4 hv;
        hv.x = *(uint32_t*)&hA; hv.y = *(uint32_t*)&hB;
        hv.z = *(uint32_t*)&hC; hv.w = *(uint32_t*)&hD;
        *(uint4*)(g_xh + i) = hv;
    } else if (bid < 10240) {
        float (*tile)[33] = (float(*)[33])sh;
        int bid2 = bid - 2048;
        int e  = bid2 >> 10;
        int d0 = ((bid2 >> 6) & 15) * 32;
        int h0 = (bid2 & 63) * 32;
        int lx = tid & 31, ly = tid >> 5;
        const float* src = w1 + ((size_t)e * Dc + d0) * Hc + h0;
        #pragma unroll
        for (int j = 0; j < 32; j += 8)
            tile[ly + j][lx] = src[(size_t)(ly + j) * Hc + lx];
        __syncthreads();
        size_t ob = ((size_t)e * Hc + h0) * Dc + d0;
        #pragma unroll
        for (int j = 0; j < 32; j += 8)
            g_w1h[ob + (size_t)(ly + j) * Dc + lx] = __float2bfloat16(tile[lx][ly + j]);
    } else if (bid < 12288) {
        int w    = (bid - 10240) * 8 + (tid >> 5);
        int lane = tid & 31;
        const float* row = w2 + (size_t)w * Dc;
        float s = 0.f;
        #pragma unroll 4
        for (int d = lane; d < Dc; d += 32) s += row[d];
        #pragma unroll
        for (int off = 16; off; off >>= 1) s += __shfl_down_sync(0xFFFFFFFFu, s, off);
        if (lane == 0) g_w2sum[w] = s;
    } else if (bid < 13312) {
        for (int i = tid; i < Dc * Ec; i += 256) sh[i] = gw[i];
        __syncthreads();
        int t    = (bid - 12288) * 8 + (tid >> 5);
        int lane = tid & 31;
        const float* xr = x + (size_t)t * Dc;
        float acc[Ec];
        #pragma unroll
        for (int e = 0; e < Ec; e++) acc[e] = 0.f;
        for (int k = lane; k < Dc; k += 32) {
            float xv = xr[k];
            float4 a = *(const float4*)&sh[k * Ec];
            float4 b = *(const float4*)&sh[k * Ec + 4];
            acc[0] += xv * a.x; acc[1] += xv * a.y; acc[2] += xv * a.z; acc[3] += xv * a.w;
            acc[4] += xv * b.x; acc[5] += xv * b.y; acc[6] += xv * b.z; acc[7] += xv * b.w;
        }
        #pragma unroll
        for (int e = 0; e < Ec; e++) {
            #pragma unroll
            for (int off = 16; off; off >>= 1)
                acc[e] += __shfl_down_sync(0xFFFFFFFFu, acc[e], off);
        }
        if (lane == 0) {
            float l[Ec];
            #pragma unroll
            for (int e = 0; e < Ec; e++) l[e] = acc[e] + gb[e];
            int i0 = 0;
            #pragma unroll
            for (int e = 1; e < Ec; e++) if (l[e] > l[i0]) i0 = e;
            int i1 = -1;
            #pragma unroll
            for (int e = 0; e < Ec; e++)
                if (e != i0 && (i1 < 0 || l[e] > l[i1])) i1 = e;
            float d  = expf(l[i1] - l[i0]);
            float s0 = 1.f / (1.f + d);
            float s1 = d / (1.f + d);
            int p0 = atomicAdd(&g_cnt[i0], 1);
            g_tok[i0 * Tc + p0] = t * 2 + 0;
            g_wgt[i0 * Tc + p0] = s0;
            int p1 = atomicAdd(&g_cnt[i1], 1);
            g_tok[i1 * Tc + p1] = t * 2 + 1;
            g_wgt[i1 * Tc + p1] = s1;
        }
    } else {
        int e = tid >> 5, lane = tid & 31;
        if (e < Ec) {
            float s = 0.f;
            for (int d = lane; d < Dc; d += 32) s += b2[e * Dc + d];
            #pragma unroll
            for (int off = 16; off; off >>= 1) s += __shfl_down_sync(0xFFFFFFFFu, s, off);
            if (lane == 0) g_b2sum[e] = s;
        }
    }
}

// ================= fused MoE FFN on mma.sync (bf16, m64n64 warp tiles) =================
// grid (64, 8), 256 threads (8 warps: warp_m = wid>>2 in 0..1, warp_n = wid&3 in 0..3)
__global__ void __launch_bounds__(256, 1)
moe_mma_kernel(const float* __restrict__ b1) {
    extern __shared__ char dsm[];
    __shared__ int   toks[MT];
    __shared__ float wgts[MT];
    __shared__ float zred[4][2][8][8];   // [warp_n][warp_m][q][group]

    const int e    = blockIdx.y;
    const int n_e  = g_cnt[e];
    const int base = blockIdx.x * MT;
    if (base >= n_e) return;

    const int tid  = threadIdx.x;
    const int wid  = tid >> 5;
    const int lane = tid & 31;
    const int warp_m = wid >> 2;   // 0..1 -> 64 rows each
    const int warp_n = wid & 3;    // 0..3 -> 64 cols each

    if (tid < MT) {
        int i = base + tid;
        toks[tid] = (i < n_e) ? g_tok[e * Tc + i] : 0;
        wgts[tid] = (i < n_e) ? g_wgt[e * Tc + i] : 0.f;
    }
    __syncthreads();

    const __nv_bfloat16* wh = g_w1h + (size_t)e * Hc * Dc;
    const float* b1e = b1 + e * Hc;
    const float* w2e = g_w2sum + e * Hc;
    const uint32_t smb = smem_u32(dsm);

    // ---- hoisted staging addresses (256 threads) ----
    const int r0  = tid >> 3;   // 0..31
    const int cch = tid & 7;    // 16B quad within 128B row
    const __nv_bfloat16* pA[4];
    const __nv_bfloat16* pB[8];
    uint32_t dA[4], dB[8];
    #pragma unroll
    for (int j = 0; j < 4; j++) {
        int m = r0 + j * 32;
        pA[j] = g_xh + (size_t)(toks[m] >> 1) * Dc + cch * 8;
        dA[j] = SWZ((uint32_t)(m * 128 + cch * 16));
    }
    #pragma unroll
    for (int j = 0; j < 8; j++) {
        int n = r0 + j * 32;
        pB[j] = wh + (size_t)n * Dc + cch * 8;
        dB[j] = SWZ((uint32_t)(n * 128 + cch * 16));
    }

    auto stage = [&](int st, int buf) {
        const int c  = st >> 3;
        const int kb = st & 7;
        const uint32_t bb = smb + (uint32_t)buf * BUF_BYTES;
        const int ko = kb * KB;
        const size_t co = (size_t)c * NCHK * Dc;
        #pragma unroll
        for (int j = 0; j < 4; j++)
            CP_ASYNC16(bb + OFF_A + dA[j], pA[j] + ko);
        #pragma unroll
        for (int j = 0; j < 8; j++)
            CP_ASYNC16(bb + OFF_B + dB[j], pB[j] + co + ko);
    };

    float acc[4][8][4];
    #pragma unroll
    for (int mt = 0; mt < 4; mt++)
        #pragma unroll
        for (int nt = 0; nt < 8; nt++)
            #pragma unroll
            for (int q = 0; q < 4; q++) acc[mt][nt][q] = 0.f;
    float zz[8] = {0.f, 0.f, 0.f, 0.f, 0.f, 0.f, 0.f, 0.f};

    // ldmatrix address components: addr = row*128 + (kbyte ^ ((row&7)<<4))
    const int a_row = warp_m * 64 + (lane & 7) + ((lane >> 3) & 1) * 8;
    const int a_kb  = (lane >> 4) * 16;
    const int b_row = warp_n * 64 + (lane & 7) + (lane >> 4) * 8;
    const int b_kb  = ((lane >> 3) & 1) * 16;
    const uint32_t a_xor = ((uint32_t)(a_row & 7)) << 4;
    const uint32_t b_xor = ((uint32_t)(b_row & 7)) << 4;

    stage(0, 0); CP_COMMIT();
    stage(1, 1); CP_COMMIT();

    int bc = 0;
    for (int it = 0; it < NITER; it++) {
        CP_WAIT1();
        __syncthreads();
        if (it + 2 < NITER) {
            int bs = bc + 2; if (bs >= 3) bs -= 3;
            stage(it + 2, bs);
        }
        CP_COMMIT();   // empty commit in tail keeps wait_group accounting uniform

        const uint32_t bb  = smb + (uint32_t)bc * BUF_BYTES;
        const uint32_t ahb = bb + OFF_A;
        const uint32_t bhb = bb + OFF_B;

        #pragma unroll
        for (int ks = 0; ks < 4; ks++) {
            uint32_t Ah[4][4];
            #pragma unroll
            for (int mt = 0; mt < 4; mt++) {
                uint32_t off = (uint32_t)((a_row + mt * 16) * 128) +
                               (((uint32_t)(a_kb + ks * 32)) ^ a_xor);
                ldsm_x4(ahb + off, Ah[mt][0], Ah[mt][1], Ah[mt][2], Ah[mt][3]);
            }
            #pragma unroll
            for (int ntp = 0; ntp < 4; ntp++) {
                uint32_t Bh[4];
                uint32_t off = (uint32_t)((b_row + ntp * 16) * 128) +
                               (((uint32_t)(b_kb + ks * 32)) ^ b_xor);
                ldsm_x4(bhb + off, Bh[0], Bh[1], Bh[2], Bh[3]);
                #pragma unroll
                for (int mt = 0; mt < 4; mt++) {
                    mma16816(acc[mt][ntp * 2 + 0], Ah[mt], &Bh[0]);
                    mma16816(acc[mt][ntp * 2 + 1], Ah[mt], &Bh[2]);
                }
            }
        }

        if ((it & 7) == 7) {
            const int c = it >> 3;
            #pragma unroll
            for (int mt = 0; mt < 4; mt++)
                #pragma unroll
                for (int nt = 0; nt < 8; nt++) {
                    int col = c * NCHK + warp_n * 64 + nt * 8 + (lane & 3) * 2;
                    float bb0 = b1e[col], bb1 = b1e[col + 1];
                    float ws0 = w2e[col], ws1 = w2e[col + 1];
                    #pragma unroll
                    for (int rh = 0; rh < 2; rh++) {
                        float a0 = acc[mt][nt][rh * 2 + 0] + bb0;
                        float a1 = acc[mt][nt][rh * 2 + 1] + bb1;
                        float g0 = 0.5f * a0 * (1.f + erff(a0 * 0.70710678118654752440f));
                        float g1 = 0.5f * a1 * (1.f + erff(a1 * 0.70710678118654752440f));
                        zz[mt * 2 + rh] += g0 * ws0 + g1 * ws1;
                        acc[mt][nt][rh * 2 + 0] = 0.f;
                        acc[mt][nt][rh * 2 + 1] = 0.f;
                    }
                }
        }
        bc++; if (bc == 3) bc = 0;
    }

    // reduce over the 4 lanes sharing a row
    #pragma unroll
    for (int q = 0; q < 8; q++) {
        zz[q] += __shfl_xor_sync(0xFFFFFFFFu, zz[q], 1);
        zz[q] += __shfl_xor_sync(0xFFFFFFFFu, zz[q], 2);
    }
    if (warp_n != 0 && (lane & 3) == 0) {
        #pragma unroll
        for (int q = 0; q < 8; q++) zred[warp_n][warp_m][q][lane >> 2] = zz[q];
    }
    __syncthreads();
    if (warp_n == 0 && (lane & 3) == 0) {
        float b2s = g_b2sum[e];
        int g = lane >> 2;
        #pragma unroll
        for (int q = 0; q < 8; q++) {
            // q = mt*2 + rh : row = warp_m*64 + mt*16 + rh*8 + g
            int row = warp_m * 64 + (q >> 1) * 16 + (q & 1) * 8 + g;
            if (base + row < n_e) {
                float z = zz[q] + zred[1][warp_m][q][g] + zred[2][warp_m][q][g]
                        + zred[3][warp_m][q][g];
                g_zpart[toks[row]] = wgts[row] * (z + b2s);
            }
        }
    }
}

// ---------------- per-batch log_softmax over S (+ counter reset for next replay) ----------------
__global__ void lse_kernel(float* __restrict__ out) {
    if (blockIdx.x == 0 && threadIdx.x < Ec) g_cnt[threadIdx.x] = 0;
    int b = blockIdx.x;
    int s = threadIdx.x;   // 1024 threads
    __shared__ float sm[Sc];
    float v = g_zpart[(b * Sc + s) * 2] + g_zpart[(b * Sc + s) * 2 + 1];
    sm[s] = v;
    __syncthreads();
    for (int off = 512; off; off >>= 1) {
        if (s < off) sm[s] = fmaxf(sm[s], sm[s + off]);
        __syncthreads();
    }
    float mx = sm[0];
    __syncthreads();
    sm[s] = expf(v - mx);
    __syncthreads();
    for (int off = 512; off; off >>= 1) {
        if (s < off) sm[s] += sm[s + off];
        __syncthreads();
    }
    out[b * Sc + s] = v - mx - logf(sm[0]);
}

// ---------------- launch ----------------
extern "C" void kernel_launch(void* const* d_in, const int* in_sizes, int n_in,
                              void* d_out, int out_size) {
    (void)in_sizes; (void)n_in; (void)out_size;
    const float* x  = (const float*)d_in[0];
    const float* gw = (const float*)d_in[1];
    const float* gb = (const float*)d_in[2];
    const float* w1 = (const float*)d_in[3];
    const float* b1 = (const float*)d_in[4];
    const float* w2 = (const float*)d_in[5];
    const float* b2 = (const float*)d_in[6];
    float* out = (float*)d_out;

    cudaFuncSetAttribute(moe_mma_kernel, cudaFuncAttributeMaxDynamicSharedMemorySize, DYN_SMEM);

    prep_kernel<<<PREP_BLOCKS, 256>>>(x, gw, gb, w1, w2, b2);
    moe_mma_kernel<<<dim3(Tc / MT, Ec), 256, DYN_SMEM>>>(b1);
    lse_kernel<<<Bc, Sc>>>(out);
}

// round 10
// speedup vs baseline: 1.6451x; 1.6451x over previous
#include <cuda_runtime.h>
#include <cuda_bf16.h>
#include <math.h>
#include <stdint.h>

// Problem constants
#define Bc   8
#define Sc   1024
#define Dc   512
#define Hc   2048
#define Ec   8
#define Tc   8192   // B*S tokens

// moe tiling: CTA = 128 entries x 256-col chunks, K staged 64 at a time
#define MT     128
#define NCHK   256                 // cols per chunk
#define KB     64                  // K elems per stage (128B rows)
#define NCHUNK (Hc / NCHK)         // 8
#define NKB    (Dc / KB)           // 8
#define NITER  (NCHUNK * NKB)      // 64

// SMEM stage layout (bytes), 2-stage pipeline
#define OFF_A   0
#define OFF_B   (16 * 1024)
#define BUF_BYTES (48 * 1024)
#define DYN_SMEM (2 * BUF_BYTES)

// ---------------- device scratch ----------------
__device__ int    g_cnt[Ec];
__device__ int    g_tok[Ec * Tc];
__device__ float  g_wgt[Ec * Tc];
__device__ float  g_zpart[Tc * 2];
__device__ float  g_w2sum[Ec * Hc];
__device__ float  g_b2sum[Ec];
__device__ __nv_bfloat16 g_w1h[(size_t)Ec * Hc * Dc];   // [e][h][d] K-major, bf16
__device__ __nv_bfloat16 g_xh[(size_t)Tc * Dc];         // bf16(x)

// ---------------- helpers ----------------
__device__ __forceinline__ uint32_t smem_u32(const void* p) {
    uint32_t a;
    asm("{ .reg .u64 t; cvta.to.shared.u64 t, %1; cvt.u32.u64 %0, t; }" : "=r"(a) : "l"(p));
    return a;
}
#define SWZ(off) ((off) ^ (((off) >> 3) & 0x70))

#define CP_ASYNC16(dst, src) \
    asm volatile("cp.async.cg.shared.global [%0], [%1], 16;" :: "r"(dst), "l"(src))
#define CP_COMMIT() asm volatile("cp.async.commit_group;" ::: "memory")
#define CP_WAIT0()  asm volatile("cp.async.wait_group 0;" ::: "memory")

__device__ __forceinline__ void ldsm_x4(uint32_t addr, uint32_t& r0, uint32_t& r1,
                                        uint32_t& r2, uint32_t& r3) {
    asm volatile("ldmatrix.sync.aligned.m8n8.x4.shared.b16 {%0,%1,%2,%3}, [%4];"
                 : "=r"(r0), "=r"(r1), "=r"(r2), "=r"(r3) : "r"(addr));
}
__device__ __forceinline__ void mma16816(float* c, const uint32_t* a, const uint32_t* b) {
    asm volatile("mma.sync.aligned.m16n8k16.row.col.f32.bf16.bf16.f32 "
                 "{%0,%1,%2,%3}, {%4,%5,%6,%7}, {%8,%9}, {%0,%1,%2,%3};"
                 : "+f"(c[0]), "+f"(c[1]), "+f"(c[2]), "+f"(c[3])
                 : "r"(a[0]), "r"(a[1]), "r"(a[2]), "r"(a[3]), "r"(b[0]), "r"(b[1]));
}

// Fast exact-grade gelu: 0.5*a*(1+erf(a/sqrt2)), erf via A&S 7.1.26 (|eps|<=1.5e-7).
__device__ __forceinline__ float gelu_fast(float a) {
    float u  = a * 0.70710678118654752440f;
    float au = fabsf(u);
    float t  = __fdividef(1.f, fmaf(0.3275911f, au, 1.f));
    float p  = t * fmaf(t, fmaf(t, fmaf(t, fmaf(t, 1.061405429f, -1.453152027f),
                                        1.421413741f), -0.284496736f), 0.254829592f);
    float er = 1.f - p * __expf(-u * u);          // erf(|u|)
    er = copysignf(er, u);
    return 0.5f * a * (1.f + er);
}

// ================= fused prep kernel =================
// blockIdx ranges:
//   [0, 2048)       : x -> bf16
//   [2048, 6144)    : w1 transpose + bf16 convert (64d x 32h tiles, uint4 stores)
//   [6144, 8192)    : w2sum
//   [8192, 9216)    : gate
//   [9216]          : b2sum
#define PREP_BLOCKS 9217

__global__ void prep_kernel(const float* __restrict__ x,
                            const float* __restrict__ gw,
                            const float* __restrict__ gb,
                            const float* __restrict__ w1,
                            const float* __restrict__ w2,
                            const float* __restrict__ b2) {
    __shared__ float sh[64 * 33];   // ~8.4 KB, aliased per section
    const int bid = blockIdx.x;
    const int tid = threadIdx.x;

    if (bid < 2048) {
        // ---- x -> bf16 (8 floats per thread) ----
        size_t i = ((size_t)bid * 256 + tid) * 8;
        float4 v0 = *(const float4*)(x + i);
        float4 v1 = *(const float4*)(x + i + 4);
        __nv_bfloat162 hA = __floats2bfloat162_rn(v0.x, v0.y);
        __nv_bfloat162 hB = __floats2bfloat162_rn(v0.z, v0.w);
        __nv_bfloat162 hC = __floats2bfloat162_rn(v1.x, v1.y);
        __nv_bfloat162 hD = __floats2bfloat162_rn(v1.z, v1.w);
        uint4 hv;
        hv.x = *(uint32_t*)&hA; hv.y = *(uint32_t*)&hB;
        hv.z = *(uint32_t*)&hC; hv.w = *(uint32_t*)&hD;
        *(uint4*)(g_xh + i) = hv;
    } else if (bid < 6144) {
        // ---- w1: [e][d][h] -> [e][h][d] bf16, 64d x 32h tile ----
        float (*tile)[33] = (float(*)[33])sh;
        int bid2 = bid - 2048;                 // [0, 4096)
        int e  = bid2 >> 9;                    // 512 blocks/expert
        int d0 = ((bid2 >> 6) & 7) * 64;
        int h0 = (bid2 & 63) * 32;
        int lx = tid & 31, ly = tid >> 5;      // lx: h-col, ly: 0..7
        const float* src = w1 + ((size_t)e * Dc + d0) * Hc + h0;
        #pragma unroll
        for (int j = 0; j < 64; j += 8)
            tile[ly + j][lx] = src[(size_t)(ly + j) * Hc + lx];
        __syncthreads();
        // write: thread -> 8 consecutive d for one h row (16B store)
        int hl = tid >> 3;          // 0..31
        int db = tid & 7;           // d block of 8
        __nv_bfloat16 v[8];
        #pragma unroll
        for (int k = 0; k < 8; k++)
            v[k] = __float2bfloat16(tile[db * 8 + k][hl]);
        *(uint4*)(g_w1h + ((size_t)e * Hc + h0 + hl) * Dc + d0 + db * 8) = *(uint4*)v;
    } else if (bid < 8192) {
        int w    = (bid - 6144) * 8 + (tid >> 5);
        int lane = tid & 31;
        const float* row = w2 + (size_t)w * Dc;
        float s = 0.f;
        #pragma unroll 4
        for (int d = lane; d < Dc; d += 32) s += row[d];
        #pragma unroll
        for (int off = 16; off; off >>= 1) s += __shfl_down_sync(0xFFFFFFFFu, s, off);
        if (lane == 0) g_w2sum[w] = s;
    } else if (bid < 9216) {
        float* sgw = sh;   // needs 4096 floats < 64*33
        // NOTE: 64*33 = 2112 floats < 4096 -> need separate handling; reuse as 2 chunks
        // gate needs gw [512][8] = 4096 floats = 16KB; sh is only ~8.4KB.
        // Load half into smem, keep other half in registers? Simpler: use two passes over k.
        // Instead: load gw into smem as bf16? Keep it simple: read gw from L1 directly.
        (void)sgw;
        int t    = (bid - 8192) * 8 + (tid >> 5);
        int lane = tid & 31;
        const float* xr = x + (size_t)t * Dc;
        float acc[Ec];
        #pragma unroll
        for (int e = 0; e < Ec; e++) acc[e] = 0.f;
        for (int k = lane; k < Dc; k += 32) {
            float xv = xr[k];
            float4 a = *(const float4*)&gw[k * Ec];
            float4 b = *(const float4*)&gw[k * Ec + 4];
            acc[0] += xv * a.x; acc[1] += xv * a.y; acc[2] += xv * a.z; acc[3] += xv * a.w;
            acc[4] += xv * b.x; acc[5] += xv * b.y; acc[6] += xv * b.z; acc[7] += xv * b.w;
        }
        #pragma unroll
        for (int e = 0; e < Ec; e++) {
            #pragma unroll
            for (int off = 16; off; off >>= 1)
                acc[e] += __shfl_down_sync(0xFFFFFFFFu, acc[e], off);
        }
        if (lane == 0) {
            float l[Ec];
            #pragma unroll
            for (int e = 0; e < Ec; e++) l[e] = acc[e] + gb[e];
            int i0 = 0;
            #pragma unroll
            for (int e = 1; e < Ec; e++) if (l[e] > l[i0]) i0 = e;
            int i1 = -1;
            #pragma unroll
            for (int e = 0; e < Ec; e++)
                if (e != i0 && (i1 < 0 || l[e] > l[i1])) i1 = e;
            float d  = expf(l[i1] - l[i0]);
            float s0 = 1.f / (1.f + d);
            float s1 = d / (1.f + d);
            int p0 = atomicAdd(&g_cnt[i0], 1);
            g_tok[i0 * Tc + p0] = t * 2 + 0;
            g_wgt[i0 * Tc + p0] = s0;
            int p1 = atomicAdd(&g_cnt[i1], 1);
            g_tok[i1 * Tc + p1] = t * 2 + 1;
            g_wgt[i1 * Tc + p1] = s1;
        }
    } else {
        int e = tid >> 5, lane = tid & 31;
        if (e < Ec) {
            float s = 0.f;
            for (int d = lane; d < Dc; d += 32) s += b2[e * Dc + d];
            #pragma unroll
            for (int off = 16; off; off >>= 1) s += __shfl_down_sync(0xFFFFFFFFu, s, off);
            if (lane == 0) g_b2sum[e] = s;
        }
    }
}

// ================= fused MoE FFN on mma.sync (bf16 single-pass) =================
// grid (64, 8), 512 threads (16 warps: warp_m = wid>>2 in 0..3, warp_n = wid&3)
__global__ void __launch_bounds__(512, 1)
moe_mma_kernel(const float* __restrict__ b1) {
    extern __shared__ char dsm[];
    __shared__ int   toks[MT];
    __shared__ float wgts[MT];
    __shared__ float zred[4][4][4][8];   // [warp_n][warp_m][q][group]

    const int e    = blockIdx.y;
    const int n_e  = g_cnt[e];
    const int base = blockIdx.x * MT;
    if (base >= n_e) return;

    const int tid  = threadIdx.x;
    const int wid  = tid >> 5;
    const int lane = tid & 31;
    const int warp_m = wid >> 2;
    const int warp_n = wid & 3;

    if (tid < MT) {
        int i = base + tid;
        toks[tid] = (i < n_e) ? g_tok[e * Tc + i] : 0;
        wgts[tid] = (i < n_e) ? g_wgt[e * Tc + i] : 0.f;
    }
    __syncthreads();

    const __nv_bfloat16* wh = g_w1h + (size_t)e * Hc * Dc;
    const float* b1e = b1 + e * Hc;
    const float* w2e = g_w2sum + e * Hc;
    const uint32_t smb = smem_u32(dsm);

    // ---- hoisted staging addresses (512 threads) ----
    const int r0  = tid >> 3;   // 0..63
    const int cch = tid & 7;    // 16B quad within 128B row
    const __nv_bfloat16* pA[2];
    const __nv_bfloat16* pB[4];
    uint32_t dA[2], dB[4];
    #pragma unroll
    for (int j = 0; j < 2; j++) {
        int m = r0 + j * 64;
        pA[j] = g_xh + (size_t)(toks[m] >> 1) * Dc + cch * 8;
        dA[j] = SWZ((uint32_t)(m * 128 + cch * 16));
    }
    #pragma unroll
    for (int j = 0; j < 4; j++) {
        int n = r0 + j * 64;
        pB[j] = wh + (size_t)n * Dc + cch * 8;
        dB[j] = SWZ((uint32_t)(n * 128 + cch * 16));
    }

    auto stage = [&](int st, int buf) {
        const int c  = st >> 3;
        const int kb = st & 7;
        const uint32_t bb = smb + (uint32_t)buf * BUF_BYTES;
        const int ko = kb * KB;
        const size_t co = (size_t)c * NCHK * Dc;
        #pragma unroll
        for (int j = 0; j < 2; j++)
            CP_ASYNC16(bb + OFF_A + dA[j], pA[j] + ko);
        #pragma unroll
        for (int j = 0; j < 4; j++)
            CP_ASYNC16(bb + OFF_B + dB[j], pB[j] + co + ko);
    };

    float acc[2][8][4];
    #pragma unroll
    for (int mt = 0; mt < 2; mt++)
        #pragma unroll
        for (int nt = 0; nt < 8; nt++)
            #pragma unroll
            for (int q = 0; q < 4; q++) acc[mt][nt][q] = 0.f;
    float zz[4] = {0.f, 0.f, 0.f, 0.f};

    // ldmatrix address components: addr = row*128 + (kbyte ^ ((row&7)<<4))
    const int a_row = warp_m * 32 + (lane & 7) + ((lane >> 3) & 1) * 8;
    const int a_kb  = (lane >> 4) * 16;
    const int b_row = warp_n * 64 + (lane & 7) + (lane >> 4) * 8;
    const int b_kb  = ((lane >> 3) & 1) * 16;
    const uint32_t a_xor = ((uint32_t)(a_row & 7)) << 4;
    const uint32_t b_xor = ((uint32_t)(b_row & 7)) << 4;

    stage(0, 0); CP_COMMIT();

    for (int it = 0; it < NITER; it++) {
        CP_WAIT0();
        __syncthreads();
        if (it + 1 < NITER) stage(it + 1, (it + 1) & 1);
        CP_COMMIT();

        const uint32_t bb  = smb + (uint32_t)(it & 1) * BUF_BYTES;
        const uint32_t ahb = bb + OFF_A;
        const uint32_t bhb = bb + OFF_B;

        #pragma unroll
        for (int ks = 0; ks < 4; ks++) {
            uint32_t Ah[2][4];
            #pragma unroll
            for (int mt = 0; mt < 2; mt++) {
                uint32_t off = (uint32_t)((a_row + mt * 16) * 128) +
                               (((uint32_t)(a_kb + ks * 32)) ^ a_xor);
                ldsm_x4(ahb + off, Ah[mt][0], Ah[mt][1], Ah[mt][2], Ah[mt][3]);
            }
            #pragma unroll
            for (int np = 0; np < 2; np++) {
                uint32_t Bh[8];
                #pragma unroll
                for (int q = 0; q < 2; q++) {
                    int ntp = np * 2 + q;
                    uint32_t off = (uint32_t)((b_row + ntp * 16) * 128) +
                                   (((uint32_t)(b_kb + ks * 32)) ^ b_xor);
                    ldsm_x4(bhb + off, Bh[q*4+0], Bh[q*4+1], Bh[q*4+2], Bh[q*4+3]);
                }
                #pragma unroll
                for (int mt = 0; mt < 2; mt++)
                    #pragma unroll
                    for (int ntl = 0; ntl < 4; ntl++)
                        mma16816(acc[mt][np * 4 + ntl], Ah[mt], &Bh[ntl*2]);
            }
        }

        if ((it & 7) == 7) {
            const int c = it >> 3;
            #pragma unroll
            for (int mt = 0; mt < 2; mt++)
                #pragma unroll
                for (int nt = 0; nt < 8; nt++) {
                    int col = c * NCHK + warp_n * 64 + nt * 8 + (lane & 3) * 2;
                    float bb0 = b1e[col], bb1 = b1e[col + 1];
                    float ws0 = w2e[col], ws1 = w2e[col + 1];
                    #pragma unroll
                    for (int rh = 0; rh < 2; rh++) {
                        float g0 = gelu_fast(acc[mt][nt][rh * 2 + 0] + bb0);
                        float g1 = gelu_fast(acc[mt][nt][rh * 2 + 1] + bb1);
                        zz[mt * 2 + rh] += g0 * ws0 + g1 * ws1;
                        acc[mt][nt][rh * 2 + 0] = 0.f;
                        acc[mt][nt][rh * 2 + 1] = 0.f;
                    }
                }
        }
    }

    // reduce over the 4 lanes sharing a row
    #pragma unroll
    for (int q = 0; q < 4; q++) {
        zz[q] += __shfl_xor_sync(0xFFFFFFFFu, zz[q], 1);
        zz[q] += __shfl_xor_sync(0xFFFFFFFFu, zz[q], 2);
    }
    if (warp_n != 0 && (lane & 3) == 0) {
        #pragma unroll
        for (int q = 0; q < 4; q++) zred[warp_n][warp_m][q][lane >> 2] = zz[q];
    }
    __syncthreads();
    if (warp_n == 0 && (lane & 3) == 0) {
        float b2s = g_b2sum[e];
        int g = lane >> 2;
        #pragma unroll
        for (int q = 0; q < 4; q++) {
            int row = warp_m * 32 + (q >> 1) * 16 + (q & 1) * 8 + g;
            if (base + row < n_e) {
                float z = zz[q] + zred[1][warp_m][q][g] + zred[2][warp_m][q][g]
                        + zred[3][warp_m][q][g];
                g_zpart[toks[row]] = wgts[row] * (z + b2s);
            }
        }
    }
}

// ---------------- per-batch log_softmax over S (+ counter reset for next replay) ----------------
__global__ void lse_kernel(float* __restrict__ out) {
    if (blockIdx.x == 0 && threadIdx.x < Ec) g_cnt[threadIdx.x] = 0;
    int b = blockIdx.x;
    int s = threadIdx.x;   // 1024 threads
    __shared__ float sm[Sc];
    float v = g_zpart[(b * Sc + s) * 2] + g_zpart[(b * Sc + s) * 2 + 1];
    sm[s] = v;
    __syncthreads();
    for (int off = 512; off; off >>= 1) {
        if (s < off) sm[s] = fmaxf(sm[s], sm[s + off]);
        __syncthreads();
    }
    float mx = sm[0];
    __syncthreads();
    sm[s] = expf(v - mx);
    __syncthreads();
    for (int off = 512; off; off >>= 1) {
        if (s < off) sm[s] += sm[s + off];
        __syncthreads();
    }
    out[b * Sc + s] = v - mx - logf(sm[0]);
}

// ---------------- launch ----------------
extern "C" void kernel_launch(void* const* d_in, const int* in_sizes, int n_in,
                              void* d_out, int out_size) {
    (void)in_sizes; (void)n_in; (void)out_size;
    const float* x  = (const float*)d_in[0];
    const float* gw = (const float*)d_in[1];
    const float* gb = (const float*)d_in[2];
    const float* w1 = (const float*)d_in[3];
    const float* b1 = (const float*)d_in[4];
    const float* w2 = (const float*)d_in[5];
    const float* b2 = (const float*)d_in[6];
    float* out = (float*)d_out;

    cudaFuncSetAttribute(moe_mma_kernel, cudaFuncAttributeMaxDynamicSharedMemorySize, DYN_SMEM);

    prep_kernel<<<PREP_BLOCKS, 256>>>(x, gw, gb, w1, w2, b2);
    moe_mma_kernel<<<dim3(Tc / MT, Ec), 512, DYN_SMEM>>>(b1);
    lse_kernel<<<Bc, Sc>>>(out);
}

// round 11
// speedup vs baseline: 1.6618x; 1.0102x over previous
#include <cuda_runtime.h>
#include <cuda_bf16.h>
#include <math.h>
#include <stdint.h>

// Problem constants
#define Bc   8
#define Sc   1024
#define Dc   512
#define Hc   2048
#define Ec   8
#define Tc   8192   // B*S tokens

// moe tiling: CTA = 128 entries x H-half (1024 cols in 128-col chunks), K staged 64
#define MT     128
#define NCHK   128                 // cols per chunk
#define KB     64                  // K elems per stage (128B rows)
#define NCHUNK 8                   // chunks per CTA (H-half 1024 / 128)
#define NKB    (Dc / KB)           // 8
#define NITER  (NCHUNK * NKB)      // 64

// SMEM stage layout (bytes), 2-stage pipeline
#define OFF_A   0
#define OFF_B   (16 * 1024)
#define BUF_BYTES (32 * 1024)
#define DYN_SMEM (2 * BUF_BYTES)

// ---------------- device scratch ----------------
__device__ int    g_cnt[Ec];
__device__ int    g_tok[Ec * Tc];
__device__ float  g_wgt[Ec * Tc];
__device__ float  g_zpart[Tc * 2];     // zero-init at load; lse re-zeroes each launch
__device__ float  g_w2sum[Ec * Hc];
__device__ float  g_b2sum[Ec];
__device__ __nv_bfloat16 g_w1h[(size_t)Ec * Hc * Dc];   // [e][h][d] K-major, bf16
__device__ __nv_bfloat16 g_xh[(size_t)Tc * Dc];         // bf16(x)

// ---------------- helpers ----------------
__device__ __forceinline__ uint32_t smem_u32(const void* p) {
    uint32_t a;
    asm("{ .reg .u64 t; cvta.to.shared.u64 t, %1; cvt.u32.u64 %0, t; }" : "=r"(a) : "l"(p));
    return a;
}
#define SWZ(off) ((off) ^ (((off) >> 3) & 0x70))

#define CP_ASYNC16(dst, src) \
    asm volatile("cp.async.cg.shared.global [%0], [%1], 16;" :: "r"(dst), "l"(src))
#define CP_COMMIT() asm volatile("cp.async.commit_group;" ::: "memory")
#define CP_WAIT0()  asm volatile("cp.async.wait_group 0;" ::: "memory")

__device__ __forceinline__ void ldsm_x4(uint32_t addr, uint32_t& r0, uint32_t& r1,
                                        uint32_t& r2, uint32_t& r3) {
    asm volatile("ldmatrix.sync.aligned.m8n8.x4.shared.b16 {%0,%1,%2,%3}, [%4];"
                 : "=r"(r0), "=r"(r1), "=r"(r2), "=r"(r3) : "r"(addr));
}
__device__ __forceinline__ void mma16816(float* c, const uint32_t* a, const uint32_t* b) {
    asm volatile("mma.sync.aligned.m16n8k16.row.col.f32.bf16.bf16.f32 "
                 "{%0,%1,%2,%3}, {%4,%5,%6,%7}, {%8,%9}, {%0,%1,%2,%3};"
                 : "+f"(c[0]), "+f"(c[1]), "+f"(c[2]), "+f"(c[3])
                 : "r"(a[0]), "r"(a[1]), "r"(a[2]), "r"(a[3]), "r"(b[0]), "r"(b[1]));
}

// Fast exact-grade gelu: 0.5*a*(1+erf(a/sqrt2)), erf via A&S 7.1.26 (|eps|<=1.5e-7).
__device__ __forceinline__ float gelu_fast(float a) {
    float u  = a * 0.70710678118654752440f;
    float au = fabsf(u);
    float t  = __fdividef(1.f, fmaf(0.3275911f, au, 1.f));
    float p  = t * fmaf(t, fmaf(t, fmaf(t, fmaf(t, 1.061405429f, -1.453152027f),
                                        1.421413741f), -0.284496736f), 0.254829592f);
    float er = 1.f - p * __expf(-u * u);          // erf(|u|)
    er = copysignf(er, u);
    return 0.5f * a * (1.f + er);
}

// ================= fused prep kernel =================
// blockIdx ranges:
//   [0, 2048)       : x -> bf16
//   [2048, 6144)    : w1 transpose + bf16 convert (64d x 32h tiles, uint4 stores)
//   [6144, 8192)    : w2sum
//   [8192, 9216)    : gate
//   [9216]          : b2sum
#define PREP_BLOCKS 9217

__global__ void prep_kernel(const float* __restrict__ x,
                            const float* __restrict__ gw,
                            const float* __restrict__ gb,
                            const float* __restrict__ w1,
                            const float* __restrict__ w2,
                            const float* __restrict__ b2) {
    __shared__ float sh[64 * 33];   // ~8.4 KB
    const int bid = blockIdx.x;
    const int tid = threadIdx.x;

    if (bid < 2048) {
        size_t i = ((size_t)bid * 256 + tid) * 8;
        float4 v0 = *(const float4*)(x + i);
        float4 v1 = *(const float4*)(x + i + 4);
        __nv_bfloat162 hA = __floats2bfloat162_rn(v0.x, v0.y);
        __nv_bfloat162 hB = __floats2bfloat162_rn(v0.z, v0.w);
        __nv_bfloat162 hC = __floats2bfloat162_rn(v1.x, v1.y);
        __nv_bfloat162 hD = __floats2bfloat162_rn(v1.z, v1.w);
        uint4 hv;
        hv.x = *(uint32_t*)&hA; hv.y = *(uint32_t*)&hB;
        hv.z = *(uint32_t*)&hC; hv.w = *(uint32_t*)&hD;
        *(uint4*)(g_xh + i) = hv;
    } else if (bid < 6144) {
        float (*tile)[33] = (float(*)[33])sh;
        int bid2 = bid - 2048;
        int e  = bid2 >> 9;
        int d0 = ((bid2 >> 6) & 7) * 64;
        int h0 = (bid2 & 63) * 32;
        int lx = tid & 31, ly = tid >> 5;
        const float* src = w1 + ((size_t)e * Dc + d0) * Hc + h0;
        #pragma unroll
        for (int j = 0; j < 64; j += 8)
            tile[ly + j][lx] = src[(size_t)(ly + j) * Hc + lx];
        __syncthreads();
        int hl = tid >> 3;
        int db = tid & 7;
        __nv_bfloat16 v[8];
        #pragma unroll
        for (int k = 0; k < 8; k++)
            v[k] = __float2bfloat16(tile[db * 8 + k][hl]);
        *(uint4*)(g_w1h + ((size_t)e * Hc + h0 + hl) * Dc + d0 + db * 8) = *(uint4*)v;
    } else if (bid < 8192) {
        int w    = (bid - 6144) * 8 + (tid >> 5);
        int lane = tid & 31;
        const float* row = w2 + (size_t)w * Dc;
        float s = 0.f;
        #pragma unroll 4
        for (int d = lane; d < Dc; d += 32) s += row[d];
        #pragma unroll
        for (int off = 16; off; off >>= 1) s += __shfl_down_sync(0xFFFFFFFFu, s, off);
        if (lane == 0) g_w2sum[w] = s;
    } else if (bid < 9216) {
        int t    = (bid - 8192) * 8 + (tid >> 5);
        int lane = tid & 31;
        const float* xr = x + (size_t)t * Dc;
        float acc[Ec];
        #pragma unroll
        for (int e = 0; e < Ec; e++) acc[e] = 0.f;
        for (int k = lane; k < Dc; k += 32) {
            float xv = xr[k];
            float4 a = *(const float4*)&gw[k * Ec];
            float4 b = *(const float4*)&gw[k * Ec + 4];
            acc[0] += xv * a.x; acc[1] += xv * a.y; acc[2] += xv * a.z; acc[3] += xv * a.w;
            acc[4] += xv * b.x; acc[5] += xv * b.y; acc[6] += xv * b.z; acc[7] += xv * b.w;
        }
        #pragma unroll
        for (int e = 0; e < Ec; e++) {
            #pragma unroll
            for (int off = 16; off; off >>= 1)
                acc[e] += __shfl_down_sync(0xFFFFFFFFu, acc[e], off);
        }
        if (lane == 0) {
            float l[Ec];
            #pragma unroll
            for (int e = 0; e < Ec; e++) l[e] = acc[e] + gb[e];
            int i0 = 0;
            #pragma unroll
            for (int e = 1; e < Ec; e++) if (l[e] > l[i0]) i0 = e;
            int i1 = -1;
            #pragma unroll
            for (int e = 0; e < Ec; e++)
                if (e != i0 && (i1 < 0 || l[e] > l[i1])) i1 = e;
            float d  = expf(l[i1] - l[i0]);
            float s0 = 1.f / (1.f + d);
            float s1 = d / (1.f + d);
            int p0 = atomicAdd(&g_cnt[i0], 1);
            g_tok[i0 * Tc + p0] = t * 2 + 0;
            g_wgt[i0 * Tc + p0] = s0;
            int p1 = atomicAdd(&g_cnt[i1], 1);
            g_tok[i1 * Tc + p1] = t * 2 + 1;
            g_wgt[i1 * Tc + p1] = s1;
        }
    } else {
        int e = tid >> 5, lane = tid & 31;
        if (e < Ec) {
            float s = 0.f;
            for (int d = lane; d < Dc; d += 32) s += b2[e * Dc + d];
            #pragma unroll
            for (int off = 16; off; off >>= 1) s += __shfl_down_sync(0xFFFFFFFFu, s, off);
            if (lane == 0) g_b2sum[e] = s;
        }
    }
}

// ================= fused MoE FFN (bf16 mma.sync, 2 CTAs/SM, H split) =================
// grid (128, 8): tile = bx>>1, H-half = bx&1. 256 threads (8 warps):
// warp_m = wid>>1 (0..3, 32 rows each), warp_n = wid&1 (0..1, 64 cols each)
__global__ void __launch_bounds__(256, 2)
moe_mma_kernel(const float* __restrict__ b1) {
    extern __shared__ char dsm[];
    __shared__ int   toks[MT];
    __shared__ float wgts[MT];
    __shared__ float zred[4][4][8];   // [warp_m][q][group] (warp_n==1 writes)

    const int e    = blockIdx.y;
    const int n_e  = g_cnt[e];
    const int base = (blockIdx.x >> 1) * MT;
    const int half = blockIdx.x & 1;
    if (base >= n_e) return;

    const int tid  = threadIdx.x;
    const int wid  = tid >> 5;
    const int lane = tid & 31;
    const int warp_m = wid >> 1;   // 0..3
    const int warp_n = wid & 1;    // 0..1

    if (tid < MT) {
        int i = base + tid;
        toks[tid] = (i < n_e) ? g_tok[e * Tc + i] : 0;
        wgts[tid] = (i < n_e) ? g_wgt[e * Tc + i] : 0.f;
    }
    __syncthreads();

    const __nv_bfloat16* wh = g_w1h + (size_t)e * Hc * Dc + (size_t)half * (Hc / 2) * Dc;
    const float* b1e = b1 + e * Hc + half * (Hc / 2);
    const float* w2e = g_w2sum + e * Hc + half * (Hc / 2);
    const uint32_t smb = smem_u32(dsm);

    // ---- hoisted staging addresses (256 threads) ----
    const int r0  = tid >> 3;   // 0..31
    const int cch = tid & 7;    // 16B quad within 128B row
    const __nv_bfloat16* pA[4];
    const __nv_bfloat16* pB[4];
    uint32_t dAB[4];            // dst offsets identical for A and B (rows j*32 + r0)
    #pragma unroll
    for (int j = 0; j < 4; j++) {
        int m = r0 + j * 32;
        pA[j]  = g_xh + (size_t)(toks[m] >> 1) * Dc + cch * 8;
        pB[j]  = wh + (size_t)m * Dc + cch * 8;
        dAB[j] = SWZ((uint32_t)(m * 128 + cch * 16));
    }

    auto stage = [&](int st, int buf) {
        const int c  = st >> 3;
        const int kb = st & 7;
        const uint32_t bb = smb + (uint32_t)buf * BUF_BYTES;
        const int ko = kb * KB;
        const size_t co = (size_t)c * NCHK * Dc;
        #pragma unroll
        for (int j = 0; j < 4; j++) {
            CP_ASYNC16(bb + OFF_A + dAB[j], pA[j] + ko);
            CP_ASYNC16(bb + OFF_B + dAB[j], pB[j] + co + ko);
        }
    };

    float acc[2][8][4];
    #pragma unroll
    for (int mt = 0; mt < 2; mt++)
        #pragma unroll
        for (int nt = 0; nt < 8; nt++)
            #pragma unroll
            for (int q = 0; q < 4; q++) acc[mt][nt][q] = 0.f;
    float zz[4] = {0.f, 0.f, 0.f, 0.f};

    // ldmatrix address components: addr = row*128 + (kbyte ^ ((row&7)<<4))
    const int a_row = warp_m * 32 + (lane & 7) + ((lane >> 3) & 1) * 8;
    const int a_kb  = (lane >> 4) * 16;
    const int b_row = warp_n * 64 + (lane & 7) + (lane >> 4) * 8;
    const int b_kb  = ((lane >> 3) & 1) * 16;
    const uint32_t a_xor = ((uint32_t)(a_row & 7)) << 4;
    const uint32_t b_xor = ((uint32_t)(b_row & 7)) << 4;

    stage(0, 0); CP_COMMIT();

    for (int it = 0; it < NITER; it++) {
        CP_WAIT0();
        __syncthreads();
        if (it + 1 < NITER) stage(it + 1, (it + 1) & 1);
        CP_COMMIT();

        const uint32_t bb  = smb + (uint32_t)(it & 1) * BUF_BYTES;
        const uint32_t ahb = bb + OFF_A;
        const uint32_t bhb = bb + OFF_B;

        #pragma unroll
        for (int ks = 0; ks < 4; ks++) {
            uint32_t Ah[2][4];
            #pragma unroll
            for (int mt = 0; mt < 2; mt++) {
                uint32_t off = (uint32_t)((a_row + mt * 16) * 128) +
                               (((uint32_t)(a_kb + ks * 32)) ^ a_xor);
                ldsm_x4(ahb + off, Ah[mt][0], Ah[mt][1], Ah[mt][2], Ah[mt][3]);
            }
            #pragma unroll
            for (int np = 0; np < 2; np++) {
                uint32_t Bh[8];
                #pragma unroll
                for (int q = 0; q < 2; q++) {
                    int ntp = np * 2 + q;
                    uint32_t off = (uint32_t)((b_row + ntp * 16) * 128) +
                                   (((uint32_t)(b_kb + ks * 32)) ^ b_xor);
                    ldsm_x4(bhb + off, Bh[q*4+0], Bh[q*4+1], Bh[q*4+2], Bh[q*4+3]);
                }
                #pragma unroll
                for (int mt = 0; mt < 2; mt++)
                    #pragma unroll
                    for (int ntl = 0; ntl < 4; ntl++)
                        mma16816(acc[mt][np * 4 + ntl], Ah[mt], &Bh[ntl*2]);
            }
        }

        if ((it & 7) == 7) {
            const int c = it >> 3;
            #pragma unroll
            for (int mt = 0; mt < 2; mt++)
                #pragma unroll
                for (int nt = 0; nt < 8; nt++) {
                    int col = c * NCHK + warp_n * 64 + nt * 8 + (lane & 3) * 2;
                    float bb0 = b1e[col], bb1 = b1e[col + 1];
                    float ws0 = w2e[col], ws1 = w2e[col + 1];
                    #pragma unroll
                    for (int rh = 0; rh < 2; rh++) {
                        float g0 = gelu_fast(acc[mt][nt][rh * 2 + 0] + bb0);
                        float g1 = gelu_fast(acc[mt][nt][rh * 2 + 1] + bb1);
                        zz[mt * 2 + rh] += g0 * ws0 + g1 * ws1;
                        acc[mt][nt][rh * 2 + 0] = 0.f;
                        acc[mt][nt][rh * 2 + 1] = 0.f;
                    }
                }
        }
    }

    // reduce over the 4 lanes sharing a row
    #pragma unroll
    for (int q = 0; q < 4; q++) {
        zz[q] += __shfl_xor_sync(0xFFFFFFFFu, zz[q], 1);
        zz[q] += __shfl_xor_sync(0xFFFFFFFFu, zz[q], 2);
    }
    if (warp_n == 1 && (lane & 3) == 0) {
        #pragma unroll
        for (int q = 0; q < 4; q++) zred[warp_m][q][lane >> 2] = zz[q];
    }
    __syncthreads();
    if (warp_n == 0 && (lane & 3) == 0) {
        float b2s = half ? 0.f : g_b2sum[e];
        int g = lane >> 2;
        #pragma unroll
        for (int q = 0; q < 4; q++) {
            int row = warp_m * 32 + (q >> 1) * 16 + (q & 1) * 8 + g;
            if (base + row < n_e) {
                float z = zz[q] + zred[warp_m][q][g];
                atomicAdd(&g_zpart[toks[row]], wgts[row] * (z + b2s));
            }
        }
    }
}

// ---------------- per-batch log_softmax over S (+ scratch reset for next replay) ----------------
__global__ void lse_kernel(float* __restrict__ out) {
    if (blockIdx.x == 0 && threadIdx.x < Ec) g_cnt[threadIdx.x] = 0;
    int b = blockIdx.x;
    int s = threadIdx.x;   // 1024 threads
    __shared__ float sm[Sc];
    int idx = (b * Sc + s) * 2;
    float v = g_zpart[idx] + g_zpart[idx + 1];
    g_zpart[idx] = 0.f;          // reset for next replay (atomicAdd accumulation)
    g_zpart[idx + 1] = 0.f;
    sm[s] = v;
    __syncthreads();
    for (int off = 512; off; off >>= 1) {
        if (s < off) sm[s] = fmaxf(sm[s], sm[s + off]);
        __syncthreads();
    }
    float mx = sm[0];
    __syncthreads();
    sm[s] = expf(v - mx);
    __syncthreads();
    for (int off = 512; off; off >>= 1) {
        if (s < off) sm[s] += sm[s + off];
        __syncthreads();
    }
    out[b * Sc + s] = v - mx - logf(sm[0]);
}

// ---------------- launch ----------------
extern "C" void kernel_launch(void* const* d_in, const int* in_sizes, int n_in,
                              void* d_out, int out_size) {
    (void)in_sizes; (void)n_in; (void)out_size;
    const float* x  = (const float*)d_in[0];
    const float* gw = (const float*)d_in[1];
    const float* gb = (const float*)d_in[2];
    const float* w1 = (const float*)d_in[3];
    const float* b1 = (const float*)d_in[4];
    const float* w2 = (const float*)d_in[5];
    const float* b2 = (const float*)d_in[6];
    float* out = (float*)d_out;

    cudaFuncSetAttribute(moe_mma_kernel, cudaFuncAttributeMaxDynamicSharedMemorySize, DYN_SMEM);

    prep_kernel<<<PREP_BLOCKS, 256>>>(x, gw, gb, w1, w2, b2);
    moe_mma_kernel<<<dim3(128, Ec), 256, DYN_SMEM>>>(b1);
    lse_kernel<<<Bc, Sc>>>(out);
}

// round 12
// speedup vs baseline: 1.6701x; 1.0050x over previous
#include <cuda_runtime.h>
#include <cuda_bf16.h>
#include <math.h>
#include <stdint.h>

// Problem constants
#define Bc   8
#define Sc   1024
#define Dc   512
#define Hc   2048
#define Ec   8
#define Tc   8192   // B*S tokens

// moe tiling: CTA = 128 entries x 256-col chunks, K staged 64 at a time
#define MT     128
#define NCHK   256                 // cols per chunk
#define KB     64                  // K elems per stage (128B rows)
#define NCHUNK (Hc / NCHK)         // 8
#define NKB    (Dc / KB)           // 8
#define NITER  (NCHUNK * NKB)      // 64

// SMEM layout: A resident (8 kb-blocks x 16KB), then 2-stage B buffers
#define A_BYTES   (128 * 1024)
#define B_STAGE   (32 * 1024)
#define DYN_SMEM  (A_BYTES + 2 * B_STAGE)   // 192 KB

// ---------------- device scratch ----------------
__device__ int    g_cnt[Ec];
__device__ int    g_tok[Ec * Tc];
__device__ float  g_wgt[Ec * Tc];
__device__ float  g_zpart[Tc * 2];
__device__ float  g_w2sum[Ec * Hc];
__device__ float  g_b2sum[Ec];
__device__ __nv_bfloat16 g_w1h[(size_t)Ec * Hc * Dc];   // [e][h][d] K-major, bf16

// ---------------- helpers ----------------
__device__ __forceinline__ uint32_t smem_u32(const void* p) {
    uint32_t a;
    asm("{ .reg .u64 t; cvta.to.shared.u64 t, %1; cvt.u32.u64 %0, t; }" : "=r"(a) : "l"(p));
    return a;
}
#define SWZ(off) ((off) ^ (((off) >> 3) & 0x70))

#define CP_ASYNC16(dst, src) \
    asm volatile("cp.async.cg.shared.global [%0], [%1], 16;" :: "r"(dst), "l"(src))
#define CP_COMMIT() asm volatile("cp.async.commit_group;" ::: "memory")
#define CP_WAIT0()  asm volatile("cp.async.wait_group 0;" ::: "memory")

__device__ __forceinline__ void ldsm_x4(uint32_t addr, uint32_t& r0, uint32_t& r1,
                                        uint32_t& r2, uint32_t& r3) {
    asm volatile("ldmatrix.sync.aligned.m8n8.x4.shared.b16 {%0,%1,%2,%3}, [%4];"
                 : "=r"(r0), "=r"(r1), "=r"(r2), "=r"(r3) : "r"(addr));
}
__device__ __forceinline__ void mma16816(float* c, const uint32_t* a, const uint32_t* b) {
    asm volatile("mma.sync.aligned.m16n8k16.row.col.f32.bf16.bf16.f32 "
                 "{%0,%1,%2,%3}, {%4,%5,%6,%7}, {%8,%9}, {%0,%1,%2,%3};"
                 : "+f"(c[0]), "+f"(c[1]), "+f"(c[2]), "+f"(c[3])
                 : "r"(a[0]), "r"(a[1]), "r"(a[2]), "r"(a[3]), "r"(b[0]), "r"(b[1]));
}

// Fast exact-grade gelu: 0.5*a*(1+erf(a/sqrt2)), erf via A&S 7.1.26 (|eps|<=1.5e-7).
__device__ __forceinline__ float gelu_fast(float a) {
    float u  = a * 0.70710678118654752440f;
    float au = fabsf(u);
    float t  = __fdividef(1.f, fmaf(0.3275911f, au, 1.f));
    float p  = t * fmaf(t, fmaf(t, fmaf(t, fmaf(t, 1.061405429f, -1.453152027f),
                                        1.421413741f), -0.284496736f), 0.254829592f);
    float er = 1.f - p * __expf(-u * u);          // erf(|u|)
    er = copysignf(er, u);
    return 0.5f * a * (1.f + er);
}

// ================= fused prep kernel =================
// blockIdx ranges:
//   [0, 4096)       : w1 transpose + bf16 convert (64d x 32h tiles, uint4 stores)
//   [4096, 6144)    : w2sum
//   [6144, 7168)    : gate
//   [7168]          : b2sum
#define PREP_BLOCKS 7169

__global__ void prep_kernel(const float* __restrict__ x,
                            const float* __restrict__ gw,
                            const float* __restrict__ gb,
                            const float* __restrict__ w1,
                            const float* __restrict__ w2,
                            const float* __restrict__ b2) {
    __shared__ float sh[64 * 33];   // ~8.4 KB
    const int bid = blockIdx.x;
    const int tid = threadIdx.x;

    if (bid < 4096) {
        // ---- w1: [e][d][h] -> [e][h][d] bf16, 64d x 32h tile ----
        float (*tile)[33] = (float(*)[33])sh;
        int e  = bid >> 9;                     // 512 blocks/expert
        int d0 = ((bid >> 6) & 7) * 64;
        int h0 = (bid & 63) * 32;
        int lx = tid & 31, ly = tid >> 5;      // lx: h-col, ly: 0..7
        const float* src = w1 + ((size_t)e * Dc + d0) * Hc + h0;
        #pragma unroll
        for (int j = 0; j < 64; j += 8)
            tile[ly + j][lx] = src[(size_t)(ly + j) * Hc + lx];
        __syncthreads();
        int hl = tid >> 3;          // 0..31
        int db = tid & 7;           // d block of 8
        __nv_bfloat16 v[8];
        #pragma unroll
        for (int k = 0; k < 8; k++)
            v[k] = __float2bfloat16(tile[db * 8 + k][hl]);
        *(uint4*)(g_w1h + ((size_t)e * Hc + h0 + hl) * Dc + d0 + db * 8) = *(uint4*)v;
    } else if (bid < 6144) {
        int w    = (bid - 4096) * 8 + (tid >> 5);
        int lane = tid & 31;
        const float* row = w2 + (size_t)w * Dc;
        float s = 0.f;
        #pragma unroll 4
        for (int d = lane; d < Dc; d += 32) s += row[d];
        #pragma unroll
        for (int off = 16; off; off >>= 1) s += __shfl_down_sync(0xFFFFFFFFu, s, off);
        if (lane == 0) g_w2sum[w] = s;
    } else if (bid < 7168) {
        int t    = (bid - 6144) * 8 + (tid >> 5);
        int lane = tid & 31;
        const float* xr = x + (size_t)t * Dc;
        float acc[Ec];
        #pragma unroll
        for (int e = 0; e < Ec; e++) acc[e] = 0.f;
        for (int k = lane; k < Dc; k += 32) {
            float xv = xr[k];
            float4 a = *(const float4*)&gw[k * Ec];
            float4 b = *(const float4*)&gw[k * Ec + 4];
            acc[0] += xv * a.x; acc[1] += xv * a.y; acc[2] += xv * a.z; acc[3] += xv * a.w;
            acc[4] += xv * b.x; acc[5] += xv * b.y; acc[6] += xv * b.z; acc[7] += xv * b.w;
        }
        #pragma unroll
        for (int e = 0; e < Ec; e++) {
            #pragma unroll
            for (int off = 16; off; off >>= 1)
                acc[e] += __shfl_down_sync(0xFFFFFFFFu, acc[e], off);
        }
        if (lane == 0) {
            float l[Ec];
            #pragma unroll
            for (int e = 0; e < Ec; e++) l[e] = acc[e] + gb[e];
            int i0 = 0;
            #pragma unroll
            for (int e = 1; e < Ec; e++) if (l[e] > l[i0]) i0 = e;
            int i1 = -1;
            #pragma unroll
            for (int e = 0; e < Ec; e++)
                if (e != i0 && (i1 < 0 || l[e] > l[i1])) i1 = e;
            float d  = expf(l[i1] - l[i0]);
            float s0 = 1.f / (1.f + d);
            float s1 = d / (1.f + d);
            int p0 = atomicAdd(&g_cnt[i0], 1);
            g_tok[i0 * Tc + p0] = t * 2 + 0;
            g_wgt[i0 * Tc + p0] = s0;
            int p1 = atomicAdd(&g_cnt[i1], 1);
            g_tok[i1 * Tc + p1] = t * 2 + 1;
            g_wgt[i1 * Tc + p1] = s1;
        }
    } else {
        int e = tid >> 5, lane = tid & 31;
        if (e < Ec) {
            float s = 0.f;
            for (int d = lane; d < Dc; d += 32) s += b2[e * Dc + d];
            #pragma unroll
            for (int off = 16; off; off >>= 1) s += __shfl_down_sync(0xFFFFFFFFu, s, off);
            if (lane == 0) g_b2sum[e] = s;
        }
    }
}

// ================= fused MoE FFN (bf16 mma.sync, A resident in SMEM) =================
// grid (64, 8), 512 threads (16 warps: warp_m = wid>>2 in 0..3, warp_n = wid&3)
__global__ void __launch_bounds__(512, 1)
moe_mma_kernel(const float* __restrict__ x, const float* __restrict__ b1) {
    extern __shared__ char dsm[];
    __shared__ int   toks[MT];
    __shared__ float wgts[MT];
    __shared__ float zred[4][4][4][8];   // [warp_n][warp_m][q][group]

    const int e    = blockIdx.y;
    const int n_e  = g_cnt[e];
    const int base = blockIdx.x * MT;
    if (base >= n_e) return;

    const int tid  = threadIdx.x;
    const int wid  = tid >> 5;
    const int lane = tid & 31;
    const int warp_m = wid >> 2;
    const int warp_n = wid & 3;

    if (tid < MT) {
        int i = base + tid;
        toks[tid] = (i < n_e) ? g_tok[e * Tc + i] : 0;
        wgts[tid] = (i < n_e) ? g_wgt[e * Tc + i] : 0.f;
    }
    __syncthreads();

    const __nv_bfloat16* wh = g_w1h + (size_t)e * Hc * Dc;
    const float* b1e = b1 + e * Hc;
    const float* w2e = g_w2sum + e * Hc;
    const uint32_t smb = smem_u32(dsm);

    const int r0  = tid >> 3;   // 0..63
    const int cch = tid & 7;    // 16B quad within 128B row

    // ---- B staging pointers (4 rows per thread) ----
    const __nv_bfloat16* pB[4];
    uint32_t dB[4];
    #pragma unroll
    for (int j = 0; j < 4; j++) {
        int n = r0 + j * 64;
        pB[j] = wh + (size_t)n * Dc + cch * 8;
        dB[j] = SWZ((uint32_t)(n * 128 + cch * 16));
    }

    auto stage_B = [&](int st, int buf) {
        const int c  = st >> 3;
        const int kb = st & 7;
        const uint32_t bb = smb + A_BYTES + (uint32_t)buf * B_STAGE;
        const int ko = kb * KB;
        const size_t co = (size_t)c * NCHK * Dc;
        #pragma unroll
        for (int j = 0; j < 4; j++)
            CP_ASYNC16(bb + dB[j], pB[j] + co + ko);
    };

    // ---- stage ALL of A once: fp32 gather -> bf16, 8 kb-blocks of 16KB ----
    #pragma unroll
    for (int j = 0; j < 2; j++) {
        int m = r0 + j * 64;
        const float* src = x + (size_t)(toks[m] >> 1) * Dc + cch * 8;
        uint32_t dsw = SWZ((uint32_t)(m * 128 + cch * 16));
        #pragma unroll
        for (int kb = 0; kb < 8; kb++) {
            float4 v0 = *(const float4*)(src + kb * KB);
            float4 v1 = *(const float4*)(src + kb * KB + 4);
            __nv_bfloat162 hA = __floats2bfloat162_rn(v0.x, v0.y);
            __nv_bfloat162 hB = __floats2bfloat162_rn(v0.z, v0.w);
            __nv_bfloat162 hC = __floats2bfloat162_rn(v1.x, v1.y);
            __nv_bfloat162 hD = __floats2bfloat162_rn(v1.z, v1.w);
            uint4 hv;
            hv.x = *(uint32_t*)&hA; hv.y = *(uint32_t*)&hB;
            hv.z = *(uint32_t*)&hC; hv.w = *(uint32_t*)&hD;
            *(uint4*)(dsm + kb * 16384 + dsw) = hv;
        }
    }

    float acc[2][8][4];
    #pragma unroll
    for (int mt = 0; mt < 2; mt++)
        #pragma unroll
        for (int nt = 0; nt < 8; nt++)
            #pragma unroll
            for (int q = 0; q < 4; q++) acc[mt][nt][q] = 0.f;
    float zz[4] = {0.f, 0.f, 0.f, 0.f};

    // ldmatrix address components: addr = row*128 + (kbyte ^ ((row&7)<<4))
    const int a_row = warp_m * 32 + (lane & 7) + ((lane >> 3) & 1) * 8;
    const int a_kb  = (lane >> 4) * 16;
    const int b_row = warp_n * 64 + (lane & 7) + (lane >> 4) * 8;
    const int b_kb  = ((lane >> 3) & 1) * 16;
    const uint32_t a_xor = ((uint32_t)(a_row & 7)) << 4;
    const uint32_t b_xor = ((uint32_t)(b_row & 7)) << 4;

    stage_B(0, 0); CP_COMMIT();

    for (int it = 0; it < NITER; it++) {
        CP_WAIT0();
        __syncthreads();          // also publishes the A STS on it==0
        if (it + 1 < NITER) stage_B(it + 1, (it + 1) & 1);
        CP_COMMIT();

        const int kb = it & 7;
        const uint32_t ahb = smb + (uint32_t)kb * 16384;
        const uint32_t bhb = smb + A_BYTES + (uint32_t)(it & 1) * B_STAGE;

        #pragma unroll
        for (int ks = 0; ks < 4; ks++) {
            uint32_t Ah[2][4];
            #pragma unroll
            for (int mt = 0; mt < 2; mt++) {
                uint32_t off = (uint32_t)((a_row + mt * 16) * 128) +
                               (((uint32_t)(a_kb + ks * 32)) ^ a_xor);
                ldsm_x4(ahb + off, Ah[mt][0], Ah[mt][1], Ah[mt][2], Ah[mt][3]);
            }
            #pragma unroll
            for (int np = 0; np < 2; np++) {
                uint32_t Bh[8];
                #pragma unroll
                for (int q = 0; q < 2; q++) {
                    int ntp = np * 2 + q;
                    uint32_t off = (uint32_t)((b_row + ntp * 16) * 128) +
                                   (((uint32_t)(b_kb + ks * 32)) ^ b_xor);
                    ldsm_x4(bhb + off, Bh[q*4+0], Bh[q*4+1], Bh[q*4+2], Bh[q*4+3]);
                }
                #pragma unroll
                for (int mt = 0; mt < 2; mt++)
                    #pragma unroll
                    for (int ntl = 0; ntl < 4; ntl++)
                        mma16816(acc[mt][np * 4 + ntl], Ah[mt], &Bh[ntl*2]);
            }
        }

        if ((it & 7) == 7) {
            const int c = it >> 3;
            #pragma unroll
            for (int mt = 0; mt < 2; mt++)
                #pragma unroll
                for (int nt = 0; nt < 8; nt++) {
                    int col = c * NCHK + warp_n * 64 + nt * 8 + (lane & 3) * 2;
                    float bb0 = b1e[col], bb1 = b1e[col + 1];
                    float ws0 = w2e[col], ws1 = w2e[col + 1];
                    #pragma unroll
                    for (int rh = 0; rh < 2; rh++) {
                        float g0 = gelu_fast(acc[mt][nt][rh * 2 + 0] + bb0);
                        float g1 = gelu_fast(acc[mt][nt][rh * 2 + 1] + bb1);
                        zz[mt * 2 + rh] += g0 * ws0 + g1 * ws1;
                        acc[mt][nt][rh * 2 + 0] = 0.f;
                        acc[mt][nt][rh * 2 + 1] = 0.f;
                    }
                }
        }
    }

    // reduce over the 4 lanes sharing a row
    #pragma unroll
    for (int q = 0; q < 4; q++) {
        zz[q] += __shfl_xor_sync(0xFFFFFFFFu, zz[q], 1);
        zz[q] += __shfl_xor_sync(0xFFFFFFFFu, zz[q], 2);
    }
    if (warp_n != 0 && (lane & 3) == 0) {
        #pragma unroll
        for (int q = 0; q < 4; q++) zred[warp_n][warp_m][q][lane >> 2] = zz[q];
    }
    __syncthreads();
    if (warp_n == 0 && (lane & 3) == 0) {
        float b2s = g_b2sum[e];
        int g = lane >> 2;
        #pragma unroll
        for (int q = 0; q < 4; q++) {
            int row = warp_m * 32 + (q >> 1) * 16 + (q & 1) * 8 + g;
            if (base + row < n_e) {
                float z = zz[q] + zred[1][warp_m][q][g] + zred[2][warp_m][q][g]
                        + zred[3][warp_m][q][g];
                g_zpart[toks[row]] = wgts[row] * (z + b2s);
            }
        }
    }
}

// ---------------- per-batch log_softmax over S (+ counter reset for next replay) ----------------
__global__ void lse_kernel(float* __restrict__ out) {
    if (blockIdx.x == 0 && threadIdx.x < Ec) g_cnt[threadIdx.x] = 0;
    int b = blockIdx.x;
    int s = threadIdx.x;   // 1024 threads
    __shared__ float sm[Sc];
    float v = g_zpart[(b * Sc + s) * 2] + g_zpart[(b * Sc + s) * 2 + 1];
    sm[s] = v;
    __syncthreads();
    for (int off = 512; off; off >>= 1) {
        if (s < off) sm[s] = fmaxf(sm[s], sm[s + off]);
        __syncthreads();
    }
    float mx = sm[0];
    __syncthreads();
    sm[s] = expf(v - mx);
    __syncthreads();
    for (int off = 512; off; off >>= 1) {
        if (s < off) sm[s] += sm[s + off];
        __syncthreads();
    }
    out[b * Sc + s] = v - mx - logf(sm[0]);
}

// ---------------- launch ----------------
extern "C" void kernel_launch(void* const* d_in, const int* in_sizes, int n_in,
                              void* d_out, int out_size) {
    (void)in_sizes; (void)n_in; (void)out_size;
    const float* x  = (const float*)d_in[0];
    const float* gw = (const float*)d_in[1];
    const float* gb = (const float*)d_in[2];
    const float* w1 = (const float*)d_in[3];
    const float* b1 = (const float*)d_in[4];
    const float* w2 = (const float*)d_in[5];
    const float* b2 = (const float*)d_in[6];
    float* out = (float*)d_out;

    cudaFuncSetAttribute(moe_mma_kernel, cudaFuncAttributeMaxDynamicSharedMemorySize, DYN_SMEM);

    prep_kernel<<<PREP_BLOCKS, 256>>>(x, gw, gb, w1, w2, b2);
    moe_mma_kernel<<<dim3(Tc / MT, Ec), 512, DYN_SMEM>>>(x, b1);
    lse_kernel<<<Bc, Sc>>>(out);
}